// round 10
// baseline (speedup 1.0000x reference)
#include <cuda_runtime.h>
#include <cuda_bf16.h>
#include <cstdint>

// DeChunkLayer collapses to a gather:
//   cum[b,s]   = inclusive cumsum of boundary_mask along s
//   out[b,s,:] = cum>0 ? compressed_states[b, cum-1, :] : 0
// Fused single kernel (R7 geometry) + run-length dedup: consecutive outputs
// that map to the same source row reuse the already-loaded registers instead
// of issuing a second LDG (~2x fewer gather loads at ~50% boundary density).

#define B_ 8
#define S_ 4096
#define D_ 1024
#define ROWS_PER_BLK 8

__global__ void __launch_bounds__(256)
fused_kernel(const float* __restrict__ cs,
             const int* __restrict__ mask,
             float* __restrict__ out)
{
    const int base = blockIdx.x * ROWS_PER_BLK;   // global (b*S+s) of first row
    const int b    = base >> 12;                  // / S_
    const int s0   = base & (S_ - 1);             // row within batch (mult of 8)
    const int t    = threadIdx.x;
    const int lane = t & 31;
    const int warp = t >> 5;

    const int* mrow = mask + (size_t)b * S_;

    // ---- 1) count boundaries in [0, s0) --------------------------------
    int cnt = 0;
    const int4* m4 = reinterpret_cast<const int4*>(mrow);
    for (int i = t; i < (s0 >> 2); i += 256) {
        int4 v = __ldg(&m4[i]);
        cnt += (v.x != 0) + (v.y != 0) + (v.z != 0) + (v.w != 0);
    }
    #pragma unroll
    for (int o = 16; o; o >>= 1)
        cnt += __shfl_xor_sync(0xffffffffu, cnt, o);

    __shared__ int ws[8];
    __shared__ int rows[ROWS_PER_BLK];
    if (lane == 0) ws[warp] = cnt;
    __syncthreads();

    // ---- 2) warp 0: total + inclusive scan of this block's 8 mask bits -
    if (warp == 0) {
        int v = (lane < 8) ? ws[lane] : 0;
        #pragma unroll
        for (int o = 4; o; o >>= 1)
            v += __shfl_xor_sync(0xffffffffu, v, o);      // lanes 0..7 -> total
        int total = __shfl_sync(0xffffffffu, v, 0);

        int m = (lane < ROWS_PER_BLK) ? (mrow[s0 + lane] != 0) : 0;
        int incl = m;
        #pragma unroll
        for (int o = 1; o < ROWS_PER_BLK; o <<= 1) {
            int n = __shfl_up_sync(0xffffffffu, incl, o);
            if (lane >= o) incl += n;
        }
        if (lane < ROWS_PER_BLK)
            rows[lane] = total + incl - 1;                // -1 => emit zeros
    }
    __syncthreads();

    // ---- 3) gather 8 rows, MLP over distinct rows only -----------------
    const float4* cs4 = reinterpret_cast<const float4*>(cs) + (size_t)b * (S_ * 256);
    float4* o4 = reinterpret_cast<float4*>(out) + (size_t)base * 256 + t;

    int r0 = rows[0], r1 = rows[1], r2 = rows[2], r3 = rows[3];
    int r4 = rows[4], r5 = rows[5], r6 = rows[6], r7 = rows[7];

    float4 v[ROWS_PER_BLK];
    const float4 zero = make_float4(0.f, 0.f, 0.f, 0.f);

    // Row 0 always materializes; row r>0 loads only if index changed.
    v[0] = (r0 < 0) ? zero : __ldg(cs4 + (size_t)r0 * 256 + t);
    if (r1 != r0) v[1] = (r1 < 0) ? zero : __ldg(cs4 + (size_t)r1 * 256 + t);
    if (r2 != r1) v[2] = (r2 < 0) ? zero : __ldg(cs4 + (size_t)r2 * 256 + t);
    if (r3 != r2) v[3] = (r3 < 0) ? zero : __ldg(cs4 + (size_t)r3 * 256 + t);
    if (r4 != r3) v[4] = (r4 < 0) ? zero : __ldg(cs4 + (size_t)r4 * 256 + t);
    if (r5 != r4) v[5] = (r5 < 0) ? zero : __ldg(cs4 + (size_t)r5 * 256 + t);
    if (r6 != r5) v[6] = (r6 < 0) ? zero : __ldg(cs4 + (size_t)r6 * 256 + t);
    if (r7 != r6) v[7] = (r7 < 0) ? zero : __ldg(cs4 + (size_t)r7 * 256 + t);

    // Propagate duplicates (register copies, after all loads are in flight).
    if (r1 == r0) v[1] = v[0];
    if (r2 == r1) v[2] = v[1];
    if (r3 == r2) v[3] = v[2];
    if (r4 == r3) v[4] = v[3];
    if (r5 == r4) v[5] = v[4];
    if (r6 == r5) v[6] = v[5];
    if (r7 == r6) v[7] = v[6];

    #pragma unroll
    for (int r = 0; r < ROWS_PER_BLK; r++)
        o4[(size_t)r * 256] = v[r];
}

// ---------------------------------------------------------------------------
extern "C" void kernel_launch(void* const* d_in, const int* in_sizes, int n_in,
                              void* d_out, int out_size)
{
    const float* cs = nullptr;
    const int*   mask = nullptr;
    for (int i = 0; i < n_in; i++) {
        if (in_sizes[i] == B_ * S_ * D_)      cs   = (const float*)d_in[i];
        else if (in_sizes[i] == B_ * S_)      mask = (const int*)d_in[i];
    }
    float* out = (float*)d_out;

    fused_kernel<<<(B_ * S_) / ROWS_PER_BLK, 256>>>(cs, mask, out);
}